// round 14
// baseline (speedup 1.0000x reference)
#include <cuda_runtime.h>
#include <cuda_fp16.h>

// COO SpMM with sorted rows — 2 kernels:
//   P  (prep, block-split, no barrier): row_ptr via bracketed lower_bound
//      (lane-parallel) + seq fp32 -> fp16 convert. [unchanged, measured fast]
//   KB: warp per row; halves take CONTIGUOUS chunks of the row's edges so
//       meta loads vectorize (int4/float4: 2 LDG.128 per 4 edges instead of
//       8 scalar LDGs). Lane owns 4 fp16 features (uint2): one LDG.64 warp
//       instr gathers 2 edges (1 L2 line each). Padded head/tail batches
//       keep MLP=4 everywhere (no serial load-use chains). fp32 accumulate;
//       cross-half shfl reduce; coalesced 256B store per row.
// Inputs: seq [50000*64 f32], vals [E f32], rows [E i32], cols [E i32]
// Output: [1, 50000, 64] f32

#define D_FEAT 64
#define MAX_NODES 50001
#define FULL 0xffffffffu
#define BRACKET 4096

__device__ int   g_row_ptr[MAX_NODES + 1];
__device__ uint2 g_seq_h[50000 * (D_FEAT / 4)];   // 4 fp16 per uint2, 6.4 MB

// ---- P: block-split prep ----
__global__ void prep_kernel(const float4* __restrict__ seq4,
                            const int* __restrict__ rows,
                            int n_edges, int n_nodes,
                            int n_search_blocks, int n_h2) {
    if ((int)blockIdx.x < n_search_blocks) {
        const int r = blockIdx.x * blockDim.x + threadIdx.x;
        if (r > n_nodes) return;
        const long long guess = (long long)r * n_edges / n_nodes;
        int lo = (int)guess - BRACKET; if (lo < 0) lo = 0;
        int hi = (int)guess + BRACKET; if (hi > n_edges) hi = n_edges;
        const int pl = (lo > 0)       ? rows[lo - 1] : -1;
        const int ph = (hi < n_edges) ? rows[hi]     : 0x7fffffff;
        if (!(pl < r && ph >= r)) { lo = 0; hi = n_edges; }
        while (lo < hi) {
            int mid = (lo + hi) >> 1;
            if (rows[mid] < r) lo = mid + 1; else hi = mid;
        }
        g_row_ptr[r] = lo;
    } else {
        const int i = (blockIdx.x - n_search_blocks) * blockDim.x + threadIdx.x;
        if (i >= n_h2) return;
        const float4 f = seq4[i];
        const __half2 h01 = __floats2half2_rn(f.x, f.y);
        const __half2 h23 = __floats2half2_rn(f.z, f.w);
        uint2 u;
        u.x = *reinterpret_cast<const unsigned int*>(&h01);
        u.y = *reinterpret_cast<const unsigned int*>(&h23);
        g_seq_h[i] = u;
    }
}

// ---- KB ----
__device__ __forceinline__ void fma_h4(float4& acc, float v, uint2 g) {
    const __half2 h01 = *reinterpret_cast<const __half2*>(&g.x);
    const __half2 h23 = *reinterpret_cast<const __half2*>(&g.y);
    const float2 f01 = __half22float2(h01);
    const float2 f23 = __half22float2(h23);
    acc.x = fmaf(v, f01.x, acc.x);
    acc.y = fmaf(v, f01.y, acc.y);
    acc.z = fmaf(v, f23.x, acc.z);
    acc.w = fmaf(v, f23.y, acc.w);
}

// Padded batch of up to 3 edges [i, i+n): indices clamped to last valid edge
// (duplicate gathers hit the same cached line), invalid slots get v=0.
// All gathers issue before any FMA -> no serial load-use chain.
__device__ __forceinline__ void edge_batch3(float4& acc, int i, int n, int last,
                                            const float* __restrict__ vals,
                                            const int* __restrict__ cols,
                                            int fl) {
    const int i0 = i;
    const int i1 = min(i + 1, last);
    const int i2 = min(i + 2, last);
    const float v0 = vals[i0];
    const float v1 = (1 < n) ? vals[i1] : 0.f;
    const float v2 = (2 < n) ? vals[i2] : 0.f;
    const uint2 x0 = g_seq_h[cols[i0] * (D_FEAT / 4) + fl];
    const uint2 x1 = g_seq_h[cols[i1] * (D_FEAT / 4) + fl];
    const uint2 x2 = g_seq_h[cols[i2] * (D_FEAT / 4) + fl];
    fma_h4(acc, v0, x0);
    fma_h4(acc, v1, x1);
    fma_h4(acc, v2, x2);
}

__global__ __launch_bounds__(128, 12)
void spmm_csr_h2_kernel(const float* __restrict__ vals,
                        const int* __restrict__ cols,
                        float* __restrict__ out,
                        int n_nodes) {
    const int row  = (blockIdx.x * blockDim.x + threadIdx.x) >> 5;
    const int lane = threadIdx.x & 31;
    const int half = lane >> 4;       // contiguous chunk: 0 = first, 1 = second
    const int fl   = lane & 15;       // feature lane: 4 fp16
    if (row >= n_nodes) return;

    const int beg  = g_row_ptr[row];
    const int end  = g_row_ptr[row + 1];
    const int len  = end - beg;
    const int lenh = (len + 1) >> 1;
    const int cbeg = beg + (half ? lenh : 0);
    const int cend = half ? end : beg + lenh;

    float4 acc = make_float4(0.f, 0.f, 0.f, 0.f);
    int i = cbeg;

    if (i < cend) {
        // Head: 0-3 edges to reach 16B alignment of cols+i / vals+i.
        int head = (4 - (i & 3)) & 3;
        head = min(head, cend - i);
        if (head > 0) {
            edge_batch3(acc, i, head, cend - 1, vals, cols, fl);
            i += head;
        }

        // Main: aligned groups of 4 edges, vectorized meta (2 x LDG.128),
        // 4 back-to-back LDG.64 gathers (each covering both halves' edges).
        #pragma unroll 2
        for (; i + 3 < cend; i += 4) {
            const int4   c4 = *reinterpret_cast<const int4*>(cols + i);
            const float4 v4 = *reinterpret_cast<const float4*>(vals + i);
            const uint2 x0 = g_seq_h[c4.x * (D_FEAT / 4) + fl];
            const uint2 x1 = g_seq_h[c4.y * (D_FEAT / 4) + fl];
            const uint2 x2 = g_seq_h[c4.z * (D_FEAT / 4) + fl];
            const uint2 x3 = g_seq_h[c4.w * (D_FEAT / 4) + fl];
            fma_h4(acc, v4.x, x0);
            fma_h4(acc, v4.y, x1);
            fma_h4(acc, v4.z, x2);
            fma_h4(acc, v4.w, x3);
        }

        // Tail: 0-3 edges, padded batch (meta lines already L1-hot).
        if (i < cend)
            edge_batch3(acc, i, cend - i, cend - 1, vals, cols, fl);
    }

    // Combine the two halves' partial sums (same 4 features).
    acc.x += __shfl_xor_sync(FULL, acc.x, 16);
    acc.y += __shfl_xor_sync(FULL, acc.y, 16);
    acc.z += __shfl_xor_sync(FULL, acc.z, 16);
    acc.w += __shfl_xor_sync(FULL, acc.w, 16);

    if (half == 0)   // 16 lanes x float4 = 256B coalesced; zeros if empty row
        reinterpret_cast<float4*>(out)[row * (D_FEAT / 4) + fl] = acc;
}

extern "C" void kernel_launch(void* const* d_in, const int* in_sizes, int n_in,
                              void* d_out, int out_size) {
    const float* seq  = (const float*)d_in[0];
    const float* vals = (const float*)d_in[1];
    const int*   rows = (const int*)d_in[2];
    const int*   cols = (const int*)d_in[3];
    float*       out  = (float*)d_out;
    const int n_edges = in_sizes[1];
    const int n_nodes = out_size / D_FEAT;   // 50000

    const int tP = 256;
    const int n_search_blocks  = (n_nodes + 1 + tP - 1) / tP;
    const int n_h2             = in_sizes[0] / 4;
    const int n_convert_blocks = (n_h2 + tP - 1) / tP;
    prep_kernel<<<n_search_blocks + n_convert_blocks, tP>>>(
        (const float4*)seq, rows, n_edges, n_nodes, n_search_blocks, n_h2);

    spmm_csr_h2_kernel<<<(n_nodes + 3) / 4, 128>>>(vals, cols, out, n_nodes);
}

// round 15
// speedup vs baseline: 1.1332x; 1.1332x over previous
#include <cuda_runtime.h>
#include <cuda_fp16.h>

// COO SpMM with sorted rows — 2 kernels:
//   P  (prep, block-split, no barrier): row_ptr via bracketed lower_bound
//      (lane-parallel) + seq fp32 -> fp16 convert. [unchanged]
//   KB: round-13 skeleton (warp/row, even/odd halves, lane = 4 fp16 feats,
//       scalar uniform meta LDGs, LDG.64 gathers = 1 L2 line/edge) with:
//       - 8-edge groups (8 gathers in flight)
//       - HFMA2 group accumulation (2 instr/edge vs 2cvt+4FFMA), folded to
//         fp32 master accumulator once per group (precision-safe).
// Inputs: seq [50000*64 f32], vals [E f32], rows [E i32], cols [E i32]
// Output: [1, 50000, 64] f32

#define D_FEAT 64
#define MAX_NODES 50001
#define FULL 0xffffffffu
#define BRACKET 4096

__device__ int   g_row_ptr[MAX_NODES + 1];
__device__ uint2 g_seq_h[50000 * (D_FEAT / 4)];   // 4 fp16 per uint2, 6.4 MB

// ---- P: block-split prep ----
__global__ void prep_kernel(const float4* __restrict__ seq4,
                            const int* __restrict__ rows,
                            int n_edges, int n_nodes,
                            int n_search_blocks, int n_h2) {
    if ((int)blockIdx.x < n_search_blocks) {
        const int r = blockIdx.x * blockDim.x + threadIdx.x;
        if (r > n_nodes) return;
        const long long guess = (long long)r * n_edges / n_nodes;
        int lo = (int)guess - BRACKET; if (lo < 0) lo = 0;
        int hi = (int)guess + BRACKET; if (hi > n_edges) hi = n_edges;
        const int pl = (lo > 0)       ? rows[lo - 1] : -1;
        const int ph = (hi < n_edges) ? rows[hi]     : 0x7fffffff;
        if (!(pl < r && ph >= r)) { lo = 0; hi = n_edges; }
        while (lo < hi) {
            int mid = (lo + hi) >> 1;
            if (rows[mid] < r) lo = mid + 1; else hi = mid;
        }
        g_row_ptr[r] = lo;
    } else {
        const int i = (blockIdx.x - n_search_blocks) * blockDim.x + threadIdx.x;
        if (i >= n_h2) return;
        const float4 f = seq4[i];
        const __half2 h01 = __floats2half2_rn(f.x, f.y);
        const __half2 h23 = __floats2half2_rn(f.z, f.w);
        uint2 u;
        u.x = *reinterpret_cast<const unsigned int*>(&h01);
        u.y = *reinterpret_cast<const unsigned int*>(&h23);
        g_seq_h[i] = u;
    }
}

// ---- KB helpers ----
__device__ __forceinline__ __half2 h2lo(uint2 g) {
    return *reinterpret_cast<const __half2*>(&g.x);
}
__device__ __forceinline__ __half2 h2hi(uint2 g) {
    return *reinterpret_cast<const __half2*>(&g.y);
}
__device__ __forceinline__ void fma_h4_f32(float4& acc, float v, uint2 g) {
    const float2 f01 = __half22float2(h2lo(g));
    const float2 f23 = __half22float2(h2hi(g));
    acc.x = fmaf(v, f01.x, acc.x);
    acc.y = fmaf(v, f01.y, acc.y);
    acc.z = fmaf(v, f23.x, acc.z);
    acc.w = fmaf(v, f23.y, acc.w);
}

__global__ __launch_bounds__(128, 10)
void spmm_csr_hfma_kernel(const float* __restrict__ vals,
                          const int* __restrict__ cols,
                          float* __restrict__ out,
                          int n_nodes) {
    const int row  = (blockIdx.x * blockDim.x + threadIdx.x) >> 5;
    const int lane = threadIdx.x & 31;
    const int half = lane >> 4;       // 0: even-position edges, 1: odd
    const int fl   = lane & 15;       // feature lane: 4 fp16
    if (row >= n_nodes) return;

    const int beg = g_row_ptr[row];
    const int end = g_row_ptr[row + 1];

    float4 acc = make_float4(0.f, 0.f, 0.f, 0.f);
    int i = beg + half;

    // Groups of 8 edges per half: 8 back-to-back LDG.64 gathers in flight;
    // HFMA2 accumulation within the group (fp16 adds over <=8 terms only),
    // folded into the fp32 master accumulator once per group.
    for (; i + 14 < end; i += 16) {
        const int c0 = cols[i]      * (D_FEAT / 4);
        const int c1 = cols[i + 2]  * (D_FEAT / 4);
        const int c2 = cols[i + 4]  * (D_FEAT / 4);
        const int c3 = cols[i + 6]  * (D_FEAT / 4);
        const int c4 = cols[i + 8]  * (D_FEAT / 4);
        const int c5 = cols[i + 10] * (D_FEAT / 4);
        const int c6 = cols[i + 12] * (D_FEAT / 4);
        const int c7 = cols[i + 14] * (D_FEAT / 4);

        const uint2 x0 = g_seq_h[c0 + fl];
        const uint2 x1 = g_seq_h[c1 + fl];
        const uint2 x2 = g_seq_h[c2 + fl];
        const uint2 x3 = g_seq_h[c3 + fl];
        const uint2 x4 = g_seq_h[c4 + fl];
        const uint2 x5 = g_seq_h[c5 + fl];
        const uint2 x6 = g_seq_h[c6 + fl];
        const uint2 x7 = g_seq_h[c7 + fl];

        const __half2 v0 = __float2half2_rn(vals[i]);
        const __half2 v1 = __float2half2_rn(vals[i + 2]);
        const __half2 v2 = __float2half2_rn(vals[i + 4]);
        const __half2 v3 = __float2half2_rn(vals[i + 6]);
        const __half2 v4 = __float2half2_rn(vals[i + 8]);
        const __half2 v5 = __float2half2_rn(vals[i + 10]);
        const __half2 v6 = __float2half2_rn(vals[i + 12]);
        const __half2 v7 = __float2half2_rn(vals[i + 14]);

        __half2 a01 = __hmul2(v0, h2lo(x0));
        __half2 a23 = __hmul2(v0, h2hi(x0));
        a01 = __hfma2(v1, h2lo(x1), a01);  a23 = __hfma2(v1, h2hi(x1), a23);
        a01 = __hfma2(v2, h2lo(x2), a01);  a23 = __hfma2(v2, h2hi(x2), a23);
        a01 = __hfma2(v3, h2lo(x3), a01);  a23 = __hfma2(v3, h2hi(x3), a23);
        a01 = __hfma2(v4, h2lo(x4), a01);  a23 = __hfma2(v4, h2hi(x4), a23);
        a01 = __hfma2(v5, h2lo(x5), a01);  a23 = __hfma2(v5, h2hi(x5), a23);
        a01 = __hfma2(v6, h2lo(x6), a01);  a23 = __hfma2(v6, h2hi(x6), a23);
        a01 = __hfma2(v7, h2lo(x7), a01);  a23 = __hfma2(v7, h2hi(x7), a23);

        const float2 f01 = __half22float2(a01);
        const float2 f23 = __half22float2(a23);
        acc.x += f01.x; acc.y += f01.y;
        acc.z += f23.x; acc.w += f23.y;
    }

    // Remainder (< 8 edges per half): fp32 path, latency amortized by tail.
    for (; i < end; i += 2) {
        const int   c = cols[i] * (D_FEAT / 4);
        const float v = vals[i];
        fma_h4_f32(acc, v, g_seq_h[c + fl]);
    }

    // Combine even/odd partial sums (same 4 features).
    acc.x += __shfl_xor_sync(FULL, acc.x, 16);
    acc.y += __shfl_xor_sync(FULL, acc.y, 16);
    acc.z += __shfl_xor_sync(FULL, acc.z, 16);
    acc.w += __shfl_xor_sync(FULL, acc.w, 16);

    if (half == 0)   // 16 lanes x float4 = 256B coalesced; zeros if empty row
        reinterpret_cast<float4*>(out)[row * (D_FEAT / 4) + fl] = acc;
}

extern "C" void kernel_launch(void* const* d_in, const int* in_sizes, int n_in,
                              void* d_out, int out_size) {
    const float* seq  = (const float*)d_in[0];
    const float* vals = (const float*)d_in[1];
    const int*   rows = (const int*)d_in[2];
    const int*   cols = (const int*)d_in[3];
    float*       out  = (float*)d_out;
    const int n_edges = in_sizes[1];
    const int n_nodes = out_size / D_FEAT;   // 50000

    const int tP = 256;
    const int n_search_blocks  = (n_nodes + 1 + tP - 1) / tP;
    const int n_h2             = in_sizes[0] / 4;
    const int n_convert_blocks = (n_h2 + tP - 1) / tP;
    prep_kernel<<<n_search_blocks + n_convert_blocks, tP>>>(
        (const float4*)seq, rows, n_edges, n_nodes, n_search_blocks, n_h2);

    spmm_csr_hfma_kernel<<<(n_nodes + 3) / 4, 128>>>(vals, cols, out, n_nodes);
}

// round 16
// speedup vs baseline: 1.1466x; 1.0118x over previous
#include <cuda_runtime.h>
#include <cuda_fp16.h>

// COO SpMM with sorted rows — 2 kernels:
//   P  (prep, block-split, no barrier): row_ptr via bracketed lower_bound
//      (lane-parallel) + seq fp32 -> fp16 convert. [unchanged]
//   KB: round-13 skeleton (warp/row, even/odd halves, lane = 4 fp16 feats,
//       scalar uniform meta LDGs, LDG.64 gathers = 1 L2 line/edge, groups
//       of 4 per half, fp32 FMA) + PADDED remainder batch: the <=3 leftover
//       edges issue as one clamped batch (duplicates hit cached lines,
//       v=0 for invalid) -> zero serial load-use chains in the kernel.
// Inputs: seq [50000*64 f32], vals [E f32], rows [E i32], cols [E i32]
// Output: [1, 50000, 64] f32

#define D_FEAT 64
#define MAX_NODES 50001
#define FULL 0xffffffffu
#define BRACKET 4096

__device__ int   g_row_ptr[MAX_NODES + 1];
__device__ uint2 g_seq_h[50000 * (D_FEAT / 4)];   // 4 fp16 per uint2, 6.4 MB

// ---- P: block-split prep ----
__global__ void prep_kernel(const float4* __restrict__ seq4,
                            const int* __restrict__ rows,
                            int n_edges, int n_nodes,
                            int n_search_blocks, int n_h2) {
    if ((int)blockIdx.x < n_search_blocks) {
        const int r = blockIdx.x * blockDim.x + threadIdx.x;
        if (r > n_nodes) return;
        const long long guess = (long long)r * n_edges / n_nodes;
        int lo = (int)guess - BRACKET; if (lo < 0) lo = 0;
        int hi = (int)guess + BRACKET; if (hi > n_edges) hi = n_edges;
        const int pl = (lo > 0)       ? rows[lo - 1] : -1;
        const int ph = (hi < n_edges) ? rows[hi]     : 0x7fffffff;
        if (!(pl < r && ph >= r)) { lo = 0; hi = n_edges; }
        while (lo < hi) {
            int mid = (lo + hi) >> 1;
            if (rows[mid] < r) lo = mid + 1; else hi = mid;
        }
        g_row_ptr[r] = lo;
    } else {
        const int i = (blockIdx.x - n_search_blocks) * blockDim.x + threadIdx.x;
        if (i >= n_h2) return;
        const float4 f = seq4[i];
        const __half2 h01 = __floats2half2_rn(f.x, f.y);
        const __half2 h23 = __floats2half2_rn(f.z, f.w);
        uint2 u;
        u.x = *reinterpret_cast<const unsigned int*>(&h01);
        u.y = *reinterpret_cast<const unsigned int*>(&h23);
        g_seq_h[i] = u;
    }
}

// ---- KB ----
__device__ __forceinline__ void fma_h4(float4& acc, float v, uint2 g) {
    const __half2 h01 = *reinterpret_cast<const __half2*>(&g.x);
    const __half2 h23 = *reinterpret_cast<const __half2*>(&g.y);
    const float2 f01 = __half22float2(h01);
    const float2 f23 = __half22float2(h23);
    acc.x = fmaf(v, f01.x, acc.x);
    acc.y = fmaf(v, f01.y, acc.y);
    acc.z = fmaf(v, f23.x, acc.z);
    acc.w = fmaf(v, f23.y, acc.w);
}

__global__ __launch_bounds__(128, 12)
void spmm_csr_h_kernel(const float* __restrict__ vals,
                       const int* __restrict__ cols,
                       float* __restrict__ out,
                       int n_nodes) {
    const int row  = (blockIdx.x * blockDim.x + threadIdx.x) >> 5;
    const int lane = threadIdx.x & 31;
    const int half = lane >> 4;       // 0: even-position edges, 1: odd
    const int fl   = lane & 15;       // feature lane: 4 fp16
    if (row >= n_nodes) return;

    const int beg = g_row_ptr[row];
    const int end = g_row_ptr[row + 1];

    float4 acc = make_float4(0.f, 0.f, 0.f, 0.f);
    int i = beg + half;

    // Main: groups of 4 edges per half; meta loads uniform within a half
    // (L1 broadcast); 4 back-to-back LDG.64 gathers (each warp instruction
    // covers 2 edges = 1 L2 line per edge).
    for (; i + 6 < end; i += 8) {
        const int c0 = cols[i]     * (D_FEAT / 4);
        const int c1 = cols[i + 2] * (D_FEAT / 4);
        const int c2 = cols[i + 4] * (D_FEAT / 4);
        const int c3 = cols[i + 6] * (D_FEAT / 4);
        const float v0 = vals[i];
        const float v1 = vals[i + 2];
        const float v2 = vals[i + 4];
        const float v3 = vals[i + 6];

        const uint2 x0 = g_seq_h[c0 + fl];
        const uint2 x1 = g_seq_h[c1 + fl];
        const uint2 x2 = g_seq_h[c2 + fl];
        const uint2 x3 = g_seq_h[c3 + fl];

        fma_h4(acc, v0, x0);
        fma_h4(acc, v1, x1);
        fma_h4(acc, v2, x2);
        fma_h4(acc, v3, x3);
    }

    // Remainder: <=3 stride-2 edges as ONE padded batch. Indices clamped to
    // the last valid position (its line is fetched anyway; extra hits are
    // L1-resident), invalid slots contribute v=0. No serial load-use chain.
    if (i < end) {
        const int i1 = min(i + 2, end - 1);
        const int i2 = min(i + 4, end - 1);
        const float v0 = vals[i];
        const float v1 = (i + 2 < end) ? vals[i1] : 0.f;
        const float v2 = (i + 4 < end) ? vals[i2] : 0.f;
        const uint2 x0 = g_seq_h[cols[i]  * (D_FEAT / 4) + fl];
        const uint2 x1 = g_seq_h[cols[i1] * (D_FEAT / 4) + fl];
        const uint2 x2 = g_seq_h[cols[i2] * (D_FEAT / 4) + fl];
        fma_h4(acc, v0, x0);
        fma_h4(acc, v1, x1);
        fma_h4(acc, v2, x2);
    }

    // Combine even/odd partial sums (same 4 features).
    acc.x += __shfl_xor_sync(FULL, acc.x, 16);
    acc.y += __shfl_xor_sync(FULL, acc.y, 16);
    acc.z += __shfl_xor_sync(FULL, acc.z, 16);
    acc.w += __shfl_xor_sync(FULL, acc.w, 16);

    if (half == 0)   // 16 lanes x float4 = 256B coalesced; zeros if empty row
        reinterpret_cast<float4*>(out)[row * (D_FEAT / 4) + fl] = acc;
}

extern "C" void kernel_launch(void* const* d_in, const int* in_sizes, int n_in,
                              void* d_out, int out_size) {
    const float* seq  = (const float*)d_in[0];
    const float* vals = (const float*)d_in[1];
    const int*   rows = (const int*)d_in[2];
    const int*   cols = (const int*)d_in[3];
    float*       out  = (float*)d_out;
    const int n_edges = in_sizes[1];
    const int n_nodes = out_size / D_FEAT;   // 50000

    const int tP = 256;
    const int n_search_blocks  = (n_nodes + 1 + tP - 1) / tP;
    const int n_h2             = in_sizes[0] / 4;
    const int n_convert_blocks = (n_h2 + tP - 1) / tP;
    prep_kernel<<<n_search_blocks + n_convert_blocks, tP>>>(
        (const float4*)seq, rows, n_edges, n_nodes, n_search_blocks, n_h2);

    spmm_csr_h_kernel<<<(n_nodes + 3) / 4, 128>>>(vals, cols, out, n_nodes);
}